// round 3
// baseline (speedup 1.0000x reference)
#include <cuda_runtime.h>
#include <cstdint>

#define TT 256
#define HH 512
#define VV 32
#define NBATCH 16

typedef unsigned long long u64;

// ---------------- device scratch (static, no allocation) ----------------
__device__ float g_Kproj[NBATCH*TT*HH];     // 8 MB
__device__ float g_q[NBATCH*HH];
__device__ float g_scores[NBATCH*TT];
__device__ float g_ctx[NBATCH*HH];
__device__ float g_h0[2][NBATCH*HH];
__device__ float g_c0[2][NBATCH*HH];
__device__ float g_h1[2][NBATCH*HH];
__device__ float g_c1[2][NBATCH*HH];

// barrier state: flags hold monotonically increasing epochs; g_epoch persists
// the base across launches (graph replays) so no reset race exists.
__device__ unsigned g_epoch;
__device__ unsigned g_flags[256];

// ---------------- helpers ----------------
union F4 { float4 v; u64 u[2]; };
union F2 { u64 u; float2 f; };

__device__ __forceinline__ void fma2(u64 &acc, u64 a, u64 b){
    asm("fma.rn.f32x2 %0, %1, %2, %0;" : "+l"(acc) : "l"(a), "l"(b));
}
__device__ __forceinline__ float wsum(float v){
#pragma unroll
    for (int o = 16; o; o >>= 1) v += __shfl_xor_sync(0xffffffffu, v, o);
    return v;
}
__device__ __forceinline__ float sigf(float x){ return 1.0f/(1.0f + __expf(-x)); }

// MUFU-free tanh: 2^(2x*log2e) via magic-round + deg-5 poly, then
// (t-1)/(t+1) with bit-magic reciprocal + 2 Newton steps. |err| ~1e-5.
__device__ __forceinline__ float tanh_fast(float x){
    float u = x * 2.8853900817779268f;            // 2*log2(e)
    u = fminf(fmaxf(u, -30.0f), 30.0f);
    float big = u + 12582912.0f;                  // 1.5*2^23 magic rounding
    int e = __float_as_int(big) - 0x4B400000;
    float fn = big - 12582912.0f;
    float f = u - fn;                             // f in [-0.5, 0.5]
    float p = 1.3333558e-3f;
    p = fmaf(p, f, 9.6181291e-3f);
    p = fmaf(p, f, 5.5504109e-2f);
    p = fmaf(p, f, 2.4022651e-1f);
    p = fmaf(p, f, 6.9314718e-1f);
    p = fmaf(p, f, 1.0f);
    float t = __int_as_float(__float_as_int(p) + (e << 23));   // 2^u
    float num = t - 1.0f;
    float den = t + 1.0f;
    float r = __uint_as_float(0x7EF311C3u - __float_as_uint(den));
    r = r * fmaf(-den, r, 2.0f);
    r = r * fmaf(-den, r, 2.0f);
    return num * r;
}

// grid-wide barrier: per-block epoch flag, first-NB-threads polling
__device__ __forceinline__ void gridbar(unsigned &ep, int NB){
    __syncthreads();
    ep++;
    if (threadIdx.x == 0){
        __threadfence();
        *((volatile unsigned*)&g_flags[blockIdx.x]) = ep;
    }
    if ((int)threadIdx.x < NB){
        while (*((volatile unsigned*)&g_flags[threadIdx.x]) < ep) { }
    }
    __threadfence();
    __syncthreads();
}

// ---------------- batch-shared GEMV row: dst[b*stride] = W_row . h[b] + bias ----
__device__ __forceinline__ void dotrow16(const float* __restrict__ Wrow,
                                         const float4* __restrict__ hs4,
                                         float bias, float* dst, int dstStride, int lane){
    u64 acc2[16];
#pragma unroll
    for (int b=0;b<16;b++) acc2[b]=0ull;
    const float4* W4 = (const float4*)Wrow;
#pragma unroll
    for (int i=0;i<4;i++){
        F4 Wv; Wv.v = W4[lane + 32*i];
#pragma unroll
        for (int b=0;b<16;b++){
            F4 X; X.v = hs4[b*128 + lane + 32*i];
            fma2(acc2[b], Wv.u[0], X.u[0]);
            fma2(acc2[b], Wv.u[1], X.u[1]);
        }
    }
#pragma unroll
    for (int b=0;b<16;b++){
        F2 z; z.u = acc2[b];
        float s = z.f.x + z.f.y;
        s = wsum(s);
        if (lane==b) dst[(size_t)b*dstStride] = s + bias;
    }
}

// ---------------- LSTM gate accumulation (4 gate rows x 16 batches) ----
template<int K>
__device__ __forceinline__ void lstm_accum(u64 acc[4][16], const float* __restrict__ W,
                                           int cell, const float* __restrict__ xs, int lane){
    constexpr int K4 = K/4;
    const float4* xs4 = (const float4*)xs;
    const float4* w0 = (const float4*)(W + (size_t)cell*K);
    const float4* w1 = (const float4*)(W + (size_t)(cell+512)*K);
    const float4* w2 = (const float4*)(W + (size_t)(cell+1024)*K);
    const float4* w3 = (const float4*)(W + (size_t)(cell+1536)*K);
#pragma unroll 2
    for (int it = 0; it < K4/32; it++){
        int c = lane + 32*it;
        F4 Wg0, Wg1, Wg2, Wg3;
        Wg0.v = w0[c]; Wg1.v = w1[c]; Wg2.v = w2[c]; Wg3.v = w3[c];
#pragma unroll
        for (int b=0;b<16;b++){
            F4 X; X.v = xs4[b*K4 + c];
            fma2(acc[0][b], Wg0.u[0], X.u[0]); fma2(acc[0][b], Wg0.u[1], X.u[1]);
            fma2(acc[1][b], Wg1.u[0], X.u[0]); fma2(acc[1][b], Wg1.u[1], X.u[1]);
            fma2(acc[2][b], Wg2.u[0], X.u[0]); fma2(acc[2][b], Wg2.u[1], X.u[1]);
            fma2(acc[3][b], Wg3.u[0], X.u[0]); fma2(acc[3][b], Wg3.u[1], X.u[1]);
        }
    }
}

__device__ __forceinline__ void lstm_finish(u64 acc[4][16], int cell,
        const float* __restrict__ bih, const float* __restrict__ bhh,
        const float* __restrict__ cprev, float* __restrict__ hout, float* __restrict__ cout_,
        int lane){
    float keep[4] = {0.f,0.f,0.f,0.f};
#pragma unroll
    for (int b=0;b<16;b++){
#pragma unroll
        for (int g=0; g<4; g++){
            F2 z; z.u = acc[g][b];
            float s = z.f.x + z.f.y;
            s = wsum(s);
            if (lane==b) keep[g]=s;
        }
    }
    if (lane < 16){
        int b = lane, idx = b*HH + cell;
        float gi = keep[0] + bih[cell       ] + bhh[cell       ];
        float gf = keep[1] + bih[cell +  512] + bhh[cell +  512];
        float gg = keep[2] + bih[cell + 1024] + bhh[cell + 1024];
        float go = keep[3] + bih[cell + 1536] + bhh[cell + 1536];
        float cc = sigf(gf)*cprev[idx] + sigf(gi)*tanh_fast(gg);
        cout_[idx] = cc;
        hout [idx] = sigf(go)*tanh_fast(cc);
    }
}

// ---------------- Kproj = enc @ Wk^T + bk  (one-time, tile-strided) ----------------
__device__ void kproj_phase(const float* __restrict__ A, const float* __restrict__ W,
                            const float* __restrict__ bias, float* __restrict__ C,
                            float* sm, int NB, int bx, int tid){
    float* As = sm;             // [16][65]
    float* Ws = sm + 16*65;     // [16][65]
    int lr = tid >> 2;
    int lk = (tid & 3) << 2;
    int tx = tid & 15, ty = tid >> 4;
    for (int tile = bx; tile < 64*8; tile += NB){
        int m0 = (tile >> 3)*64, n0 = (tile & 7)*64;
        float acc[4][4];
#pragma unroll
        for (int i=0;i<4;i++)
#pragma unroll
            for (int j=0;j<4;j++) acc[i][j]=0.f;
        for (int k0 = 0; k0 < HH; k0 += 16){
            float4 a4 = *(const float4*)(A + (size_t)(m0+lr)*HH + k0 + lk);
            float4 w4 = *(const float4*)(W + (size_t)(n0+lr)*HH + k0 + lk);
            __syncthreads();
            As[(lk+0)*65+lr]=a4.x; As[(lk+1)*65+lr]=a4.y; As[(lk+2)*65+lr]=a4.z; As[(lk+3)*65+lr]=a4.w;
            Ws[(lk+0)*65+lr]=w4.x; Ws[(lk+1)*65+lr]=w4.y; Ws[(lk+2)*65+lr]=w4.z; Ws[(lk+3)*65+lr]=w4.w;
            __syncthreads();
#pragma unroll
            for (int kk=0; kk<16; kk++){
                float av[4], wv[4];
#pragma unroll
                for (int i=0;i<4;i++){ av[i]=As[kk*65 + ty*4+i]; wv[i]=Ws[kk*65 + tx*4+i]; }
#pragma unroll
                for (int i=0;i<4;i++)
#pragma unroll
                    for (int j=0;j<4;j++) acc[i][j] += av[i]*wv[j];
            }
        }
#pragma unroll
        for (int i=0;i<4;i++){
            int m = m0 + ty*4 + i;
#pragma unroll
            for (int j=0;j<4;j++){
                int n = n0 + tx*4 + j;
                C[(size_t)m*HH + n] = acc[i][j] + bias[n];
            }
        }
        __syncthreads();
    }
}

// ---------------- the persistent kernel ----------------
__global__ __launch_bounds__(256, 1)
void decoder_persistent(const float* __restrict__ enc, const float* __restrict__ h0in,
                        const float* __restrict__ c0in,
                        const float* __restrict__ Wq, const float* __restrict__ bq,
                        const float* __restrict__ Wk, const float* __restrict__ bk,
                        const float* __restrict__ v,
                        const float* __restrict__ Wih0, const float* __restrict__ bih0,
                        const float* __restrict__ Whh0, const float* __restrict__ bhh0,
                        const float* __restrict__ Wih1, const float* __restrict__ bih1,
                        const float* __restrict__ Whh1, const float* __restrict__ bhh1,
                        const float* __restrict__ Wout, const float* __restrict__ bout,
                        float* __restrict__ out)
{
    extern __shared__ float sm[];
    const int tid = threadIdx.x, bx = blockIdx.x, NB = gridDim.x;
    const int lane = tid & 31, w = tid >> 5;
    const int NW = NB * 8;
    unsigned ep = g_epoch;

    // ---- phase -1: state init + Kproj precompute ----
    for (int i = bx*256 + tid; i < NBATCH*HH; i += NB*256){
        g_h0[0][i] = h0in[i];
        g_h1[0][i] = h0in[NBATCH*HH + i];
        g_c0[0][i] = c0in[i];
        g_c1[0][i] = c0in[NBATCH*HH + i];
    }
    kproj_phase(enc, Wk, bk, g_Kproj, sm, NB, bx, tid);
    gridbar(ep, NB);

    for (int t = 0; t < TT; t++){
        const int p = t & 1, np = p ^ 1;

        // ---- phase A: q = h1@Wq^T + bq ; logits[t-1] = h1@Wout^T + bout ----
        {
            float4* hs4 = (float4*)sm;
            const float4* hsrc = (const float4*)g_h1[p];
            for (int i = tid; i < 2048; i += 256) hs4[i] = hsrc[i];
            __syncthreads();
            int task = w*NB + bx;
            if (task < 512){
                dotrow16(Wq + (size_t)task*HH, hs4, bq[task], g_q + task, HH, lane);
            } else if (task < 544 && t > 0){
                int r = task - 512;
                dotrow16(Wout + (size_t)r*HH, hs4, bout[r],
                         out + (size_t)(t-1)*VV + r, TT*VV, lane);
            }
        }
        gridbar(ep, NB);

        // ---- phase B: scores[b,tau] = sum_h v[h]*tanh(q[b,h]+Kproj[b,tau,h]) ----
        {
            float4* qs4 = (float4*)sm;                 // [16][128] float4
            float*  vs  = sm + NBATCH*HH;              // [512]
            const float4* qsrc = (const float4*)g_q;
            for (int i = tid; i < 2048; i += 256) qs4[i] = qsrc[i];
            for (int i = tid; i < HH;  i += 256) vs[i] = v[i];
            __syncthreads();
            const float4* vs4 = (const float4*)vs;
            for (int task = w*NB + bx; task < NBATCH*TT; task += NW){
                int b = task >> 8;
                const float4* Kp = (const float4*)(g_Kproj + (size_t)task*HH);
                float acc = 0.f;
#pragma unroll
                for (int i = 0; i < 4; i++){
                    int c = lane + 32*i;
                    float4 k4 = Kp[c];
                    float4 q4 = qs4[b*128 + c];
                    float4 v4 = vs4[c];
                    acc += v4.x * tanh_fast(q4.x + k4.x);
                    acc += v4.y * tanh_fast(q4.y + k4.y);
                    acc += v4.z * tanh_fast(q4.z + k4.z);
                    acc += v4.w * tanh_fast(q4.w + k4.w);
                }
                acc = wsum(acc);
                if (lane == 0) g_scores[task] = acc;
            }
        }
        gridbar(ep, NB);

        // ---- phase C: softmax over T + ctx = w @ enc (128 tasks: 16b x 8 h-chunks) ----
        {
            float* sW = sm;          // exp weights [256]
            float* sR = sm + 256;    // reduction   [256]
            float* sP = sm + 512;    // partials    [256]
            for (int task = bx; task < 128; task += NB){
                int b = task >> 3, hc = (task & 7) * 64;
                float s = g_scores[b*TT + tid];
                sR[tid] = s; __syncthreads();
                for (int st = 128; st > 0; st >>= 1){
                    if (tid < st) sR[tid] = fmaxf(sR[tid], sR[tid+st]);
                    __syncthreads();
                }
                float mx = sR[0]; __syncthreads();
                float e = __expf(s - mx);
                sW[tid] = e; sR[tid] = e; __syncthreads();
                for (int st = 128; st > 0; st >>= 1){
                    if (tid < st) sR[tid] += sR[tid+st];
                    __syncthreads();
                }
                float rz = 1.f / sR[0];
                int h = hc + (tid & 63), stripe = tid >> 6;
                const float* ep_ = enc + ((size_t)(b*TT) + stripe*64)*HH + h;
                float acc = 0.f;
#pragma unroll 8
                for (int tt = 0; tt < 64; tt++) acc += sW[stripe*64 + tt] * ep_[(size_t)tt*HH];
                sP[tid] = acc; __syncthreads();
                if (tid < 64)
                    g_ctx[b*HH + hc + tid] = (sP[tid] + sP[tid+64] + sP[tid+128] + sP[tid+192]) * rz;
                __syncthreads();
            }
        }
        gridbar(ep, NB);

        // ---- phase D: LSTM layer 0, x = [enc_t | ctx] (K=1024) ----
        {
            float4* xs4 = (float4*)sm;                    // [16][256] float4 = 64KB
            float4* hs4 = (float4*)(sm + NBATCH*1024);    // [16][128] float4 = 32KB
            const float4* enc4 = (const float4*)enc;
            const float4* ctx4 = (const float4*)g_ctx;
            for (int i = tid; i < 4096; i += 256){
                int b = i >> 8, r = i & 255;
                xs4[i] = (r < 128) ? enc4[(size_t)(b*TT + t)*128 + r]
                                   : ctx4[b*128 + (r - 128)];
            }
            const float4* hsrc = (const float4*)g_h0[p];
            for (int i = tid; i < 2048; i += 256) hs4[i] = hsrc[i];
            __syncthreads();
            int task = w*NB + bx;
            if (task < 512){
                u64 acc[4][16];
#pragma unroll
                for (int g=0; g<4; g++)
#pragma unroll
                    for (int b=0; b<16; b++) acc[g][b] = 0ull;
                lstm_accum<1024>(acc, Wih0, task, sm, lane);
                lstm_accum<512 >(acc, Whh0, task, sm + NBATCH*1024, lane);
                lstm_finish(acc, task, bih0, bhh0, g_c0[p], g_h0[np], g_c0[np], lane);
            }
        }
        gridbar(ep, NB);

        // ---- phase E: LSTM layer 1, x = h0_new (K=512) ----
        {
            float4* xs4 = (float4*)sm;                    // [16][128] float4
            float4* hs4 = (float4*)(sm + NBATCH*HH);      // [16][128] float4
            const float4* xsrc = (const float4*)g_h0[np];
            const float4* hsrc = (const float4*)g_h1[p];
            for (int i = tid; i < 2048; i += 256){ xs4[i] = xsrc[i]; hs4[i] = hsrc[i]; }
            __syncthreads();
            int task = w*NB + bx;
            if (task < 512){
                u64 acc[4][16];
#pragma unroll
                for (int g=0; g<4; g++)
#pragma unroll
                    for (int b=0; b<16; b++) acc[g][b] = 0ull;
                lstm_accum<512>(acc, Wih1, task, sm, lane);
                lstm_accum<512>(acc, Whh1, task, sm + NBATCH*HH, lane);
                lstm_finish(acc, task, bih1, bhh1, g_c1[p], g_h1[np], g_c1[np], lane);
            }
        }
        gridbar(ep, NB);
    }

    // ---- final logits for t = 255 (state parity 0 after step 255) ----
    {
        float4* hs4 = (float4*)sm;
        const float4* hsrc = (const float4*)g_h1[0];
        for (int i = tid; i < 2048; i += 256) hs4[i] = hsrc[i];
        __syncthreads();
        int task = w*NB + bx;
        if (task >= 512 && task < 544){
            int r = task - 512;
            dotrow16(Wout + (size_t)r*HH, hs4, bout[r],
                     out + (size_t)(TT-1)*VV + r, TT*VV, lane);
        }
    }

    if (bx == 0 && tid == 0) g_epoch = ep;   // persist epoch base for next launch
}

// ---------------- launch ----------------
extern "C" void kernel_launch(void* const* d_in, const int* in_sizes, int n_in,
                              void* d_out, int out_size){
    const float* enc   = (const float*)d_in[0];
    const float* h0in  = (const float*)d_in[1];
    const float* c0in  = (const float*)d_in[2];
    // d_in[3] = audio_lengths (unused by the reference math)
    const float* Wq    = (const float*)d_in[4];
    const float* bq    = (const float*)d_in[5];
    const float* Wk    = (const float*)d_in[6];
    const float* bk    = (const float*)d_in[7];
    const float* v     = (const float*)d_in[8];
    // d_in[9] = vb (shift-invariant under softmax; omitted)
    const float* Wih0  = (const float*)d_in[10];
    const float* bih0  = (const float*)d_in[11];
    const float* Whh0  = (const float*)d_in[12];
    const float* bhh0  = (const float*)d_in[13];
    const float* Wih1  = (const float*)d_in[14];
    const float* bih1  = (const float*)d_in[15];
    const float* Whh1  = (const float*)d_in[16];
    const float* bhh1  = (const float*)d_in[17];
    const float* Wout  = (const float*)d_in[18];
    const float* bout  = (const float*)d_in[19];
    float* out = (float*)d_out;

    int nsm = 148;
    cudaDeviceGetAttribute(&nsm, cudaDevAttrMultiProcessorCount, 0);
    if (nsm > 256) nsm = 256;       // flags array bound
    if (nsm < 68)  nsm = 68;        // need 8*NB >= 544 warp tasks

    const int SMEM = (NBATCH*1024 + NBATCH*512) * 4;   // 98304 bytes (phase D peak)
    cudaFuncSetAttribute(decoder_persistent, cudaFuncAttributeMaxDynamicSharedMemorySize, SMEM);

    decoder_persistent<<<nsm, 256, SMEM>>>(enc, h0in, c0in, Wq, bq, Wk, bk, v,
                                           Wih0, bih0, Whh0, bhh0,
                                           Wih1, bih1, Whh1, bhh1,
                                           Wout, bout, out);
}

// round 5
// speedup vs baseline: 1.7177x; 1.7177x over previous
#include <cuda_runtime.h>
#include <cstdint>

#define TT 256
#define HH 512
#define VV 32
#define NBATCH 16

typedef unsigned long long u64;

// ---------------- device scratch (static, no allocation) ----------------
__device__ float g_Kproj[NBATCH*TT*HH];     // 8 MB
__device__ float g_q[NBATCH*HH];
__device__ float g_scores[NBATCH*TT];
__device__ float g_ctx[NBATCH*HH];
__device__ float g_h0[2][NBATCH*HH];
__device__ float g_c0[2][NBATCH*HH];
__device__ float g_h1[2][NBATCH*HH];
__device__ float g_c1[2][NBATCH*HH];

// barrier state: monotonic across launches (graph replays) -> no reset race
__device__ unsigned g_epoch;
__device__ unsigned g_arrive;
__device__ unsigned g_release;

// ---------------- helpers ----------------
union F4 { float4 v; u64 u[2]; };
union F2 { u64 u; float2 f; };

__device__ __forceinline__ void fma2(u64 &acc, u64 a, u64 b){
    asm("fma.rn.f32x2 %0, %1, %2, %0;" : "+l"(acc) : "l"(a), "l"(b));
}
__device__ __forceinline__ float wsum(float v){
#pragma unroll
    for (int o = 16; o; o >>= 1) v += __shfl_xor_sync(0xffffffffu, v, o);
    return v;
}
__device__ __forceinline__ float wmax(float v){
#pragma unroll
    for (int o = 16; o; o >>= 1) v = fmaxf(v, __shfl_xor_sync(0xffffffffu, v, o));
    return v;
}
__device__ __forceinline__ float sigf(float x){ return 1.0f/(1.0f + __expf(-x)); }

// MUFU-free tanh: 2^(2x*log2e) via magic-round + deg-5 poly, then
// (t-1)/(t+1) with bit-magic reciprocal + 2 Newton steps. |err| ~1e-5.
__device__ __forceinline__ float tanh_fast(float x){
    float u = x * 2.8853900817779268f;            // 2*log2(e)
    u = fminf(fmaxf(u, -30.0f), 30.0f);
    float big = u + 12582912.0f;                  // 1.5*2^23 magic rounding
    int e = __float_as_int(big) - 0x4B400000;
    float fn = big - 12582912.0f;
    float f = u - fn;                             // f in [-0.5, 0.5]
    float p = 1.3333558e-3f;
    p = fmaf(p, f, 9.6181291e-3f);
    p = fmaf(p, f, 5.5504109e-2f);
    p = fmaf(p, f, 2.4022651e-1f);
    p = fmaf(p, f, 6.9314718e-1f);
    p = fmaf(p, f, 1.0f);
    float t = __int_as_float(__float_as_int(p) + (e << 23));   // 2^u
    float num = t - 1.0f;
    float den = t + 1.0f;
    float r = __uint_as_float(0x7EF311C3u - __float_as_uint(den));
    r = r * fmaf(-den, r, 2.0f);
    r = r * fmaf(-den, r, 2.0f);
    return num * r;
}

// grid barrier: atomic arrive + single release flag; __threadfence (gpu scope)
// gives release/acquire ordering across SMs.
__device__ __forceinline__ void gridbar(unsigned &ep, int NB){
    __syncthreads();
    ep++;
    if (threadIdx.x == 0){
        __threadfence();                               // release my data
        unsigned prev = atomicAdd(&g_arrive, 1u);
        if (prev + 1u == ep * (unsigned)NB){
            __threadfence();                           // order count-read -> release store
            *(volatile unsigned*)&g_release = ep;
        } else {
            while (*(volatile unsigned*)&g_release < ep) __nanosleep(40);
        }
        __threadfence();                               // acquire
    }
    __syncthreads();
}

// ---------------- batch-shared GEMV row (16 batches, W prefetched) ----------
__device__ __forceinline__ void dotrow16(const float* __restrict__ Wrow,
                                         const float4* __restrict__ hs4,
                                         float bias, float* dst, int dstStride, int lane){
    u64 acc2[16];
#pragma unroll
    for (int b=0;b<16;b++) acc2[b]=0ull;
    const float4* W4 = (const float4*)Wrow;
    F4 Wv[4];
#pragma unroll
    for (int i=0;i<4;i++) Wv[i].v = __ldcg(W4 + lane + 32*i);
#pragma unroll
    for (int i=0;i<4;i++){
#pragma unroll
        for (int b=0;b<16;b++){
            F4 X; X.v = hs4[b*128 + lane + 32*i];
            fma2(acc2[b], Wv[i].u[0], X.u[0]);
            fma2(acc2[b], Wv[i].u[1], X.u[1]);
        }
    }
#pragma unroll
    for (int b=0;b<16;b++){
        F2 z; z.u = acc2[b];
        float s = z.f.x + z.f.y;
        s = wsum(s);
        if (lane==b) dst[(size_t)b*dstStride] = s + bias;
    }
}

// ---------------- LSTM gate accumulation: 4 gates x 8 batches (batch-half) ----
// W loads grouped 16-deep (1KB in flight per warp) to keep L2 streaming fed.
template<int K>
__device__ __forceinline__ void accum_half(u64 acc[4][8], const float* __restrict__ W,
                                           int row, const float4* __restrict__ xb, int lane){
    constexpr int K4 = K/4;
    const float4* w0 = (const float4*)(W + (size_t)row*K);
    const float4* w1 = (const float4*)(W + (size_t)(row+512)*K);
    const float4* w2 = (const float4*)(W + (size_t)(row+1024)*K);
    const float4* w3 = (const float4*)(W + (size_t)(row+1536)*K);
#pragma unroll
    for (int g = 0; g < K4/128; g++){
        F4 Wb[4][4];
#pragma unroll
        for (int it = 0; it < 4; it++){
            int c = lane + 32*(g*4+it);
            Wb[it][0].v = __ldcg(w0 + c);
            Wb[it][1].v = __ldcg(w1 + c);
            Wb[it][2].v = __ldcg(w2 + c);
            Wb[it][3].v = __ldcg(w3 + c);
        }
#pragma unroll
        for (int it = 0; it < 4; it++){
            int c = lane + 32*(g*4+it);
#pragma unroll
            for (int b = 0; b < 8; b++){
                F4 X; X.v = xb[b*K4 + c];
                fma2(acc[0][b], Wb[it][0].u[0], X.u[0]); fma2(acc[0][b], Wb[it][0].u[1], X.u[1]);
                fma2(acc[1][b], Wb[it][1].u[0], X.u[0]); fma2(acc[1][b], Wb[it][1].u[1], X.u[1]);
                fma2(acc[2][b], Wb[it][2].u[0], X.u[0]); fma2(acc[2][b], Wb[it][2].u[1], X.u[1]);
                fma2(acc[3][b], Wb[it][3].u[0], X.u[0]); fma2(acc[3][b], Wb[it][3].u[1], X.u[1]);
            }
        }
    }
}

__device__ __forceinline__ void finish_half(u64 acc[4][8], int cell, int bh,
        const float* __restrict__ bih, const float* __restrict__ bhh,
        const float* __restrict__ cprev, float* __restrict__ hout, float* __restrict__ cout_,
        int lane){
    float keep[4] = {0.f,0.f,0.f,0.f};
#pragma unroll
    for (int b=0;b<8;b++){
#pragma unroll
        for (int g=0; g<4; g++){
            F2 z; z.u = acc[g][b];
            float s = z.f.x + z.f.y;
            s = wsum(s);
            if (lane == b) keep[g] = s;
        }
    }
    if (lane < 8){
        int b = bh*8 + lane, idx = b*HH + cell;
        float gi = keep[0] + bih[cell       ] + bhh[cell       ];
        float gf = keep[1] + bih[cell +  512] + bhh[cell +  512];
        float gg = keep[2] + bih[cell + 1024] + bhh[cell + 1024];
        float go = keep[3] + bih[cell + 1536] + bhh[cell + 1536];
        float cc = sigf(gf)*cprev[idx] + sigf(gi)*tanh_fast(gg);
        cout_[idx] = cc;
        hout [idx] = sigf(go)*tanh_fast(cc);
    }
}

// ---------------- Kproj = enc @ Wk^T + bk  (one-time, tile-strided) ----------------
__device__ void kproj_phase(const float* __restrict__ A, const float* __restrict__ W,
                            const float* __restrict__ bias, float* __restrict__ C,
                            float* sm, int NB, int bx, int tid){
    float* As = sm;             // [16][65]
    float* Ws = sm + 16*65;     // [16][65]
    int lr = tid >> 2;
    int lk = (tid & 3) << 2;
    int tx = tid & 15, ty = tid >> 4;
    for (int tile = bx; tile < 64*8; tile += NB){
        int m0 = (tile >> 3)*64, n0 = (tile & 7)*64;
        float acc[4][4];
#pragma unroll
        for (int i=0;i<4;i++)
#pragma unroll
            for (int j=0;j<4;j++) acc[i][j]=0.f;
        for (int k0 = 0; k0 < HH; k0 += 16){
            float4 a4 = *(const float4*)(A + (size_t)(m0+lr)*HH + k0 + lk);
            float4 w4 = *(const float4*)(W + (size_t)(n0+lr)*HH + k0 + lk);
            __syncthreads();
            As[(lk+0)*65+lr]=a4.x; As[(lk+1)*65+lr]=a4.y; As[(lk+2)*65+lr]=a4.z; As[(lk+3)*65+lr]=a4.w;
            Ws[(lk+0)*65+lr]=w4.x; Ws[(lk+1)*65+lr]=w4.y; Ws[(lk+2)*65+lr]=w4.z; Ws[(lk+3)*65+lr]=w4.w;
            __syncthreads();
#pragma unroll
            for (int kk=0; kk<16; kk++){
                float av[4], wv[4];
#pragma unroll
                for (int i=0;i<4;i++){ av[i]=As[kk*65 + ty*4+i]; wv[i]=Ws[kk*65 + tx*4+i]; }
#pragma unroll
                for (int i=0;i<4;i++)
#pragma unroll
                    for (int j=0;j<4;j++) acc[i][j] += av[i]*wv[j];
            }
        }
#pragma unroll
        for (int i=0;i<4;i++){
            int m = m0 + ty*4 + i;
#pragma unroll
            for (int j=0;j<4;j++){
                int n = n0 + tx*4 + j;
                C[(size_t)m*HH + n] = acc[i][j] + bias[n];
            }
        }
        __syncthreads();
    }
}

// ---------------- the persistent kernel ----------------
__global__ __launch_bounds__(256, 1)
void decoder_persistent(const float* __restrict__ enc, const float* __restrict__ h0in,
                        const float* __restrict__ c0in,
                        const float* __restrict__ Wq, const float* __restrict__ bq,
                        const float* __restrict__ Wk, const float* __restrict__ bk,
                        const float* __restrict__ v,
                        const float* __restrict__ Wih0, const float* __restrict__ bih0,
                        const float* __restrict__ Whh0, const float* __restrict__ bhh0,
                        const float* __restrict__ Wih1, const float* __restrict__ bih1,
                        const float* __restrict__ Whh1, const float* __restrict__ bhh1,
                        const float* __restrict__ Wout, const float* __restrict__ bout,
                        float* __restrict__ out)
{
    extern __shared__ float sm[];
    const int tid = threadIdx.x, bx = blockIdx.x, NB = gridDim.x;
    const int lane = tid & 31, w = tid >> 5;
    const int NW = NB * 8;
    const int wid0 = w*NB + bx;     // global warp id (block-strided for load balance)
    unsigned ep = g_epoch;

    // ---- phase -1: state init + Kproj precompute ----
    for (int i = bx*256 + tid; i < NBATCH*HH; i += NB*256){
        g_h0[0][i] = h0in[i];
        g_h1[0][i] = h0in[NBATCH*HH + i];
        g_c0[0][i] = c0in[i];
        g_c1[0][i] = c0in[NBATCH*HH + i];
    }
    kproj_phase(enc, Wk, bk, g_Kproj, sm, NB, bx, tid);
    gridbar(ep, NB);

    for (int t = 0; t < TT; t++){
        const int p = t & 1, np = p ^ 1;

        // ---- phase A: q = h1@Wq^T + bq ; logits[t-1] = h1@Wout^T + bout ----
        {
            float4* hs4 = (float4*)sm;
            const float4* hsrc = (const float4*)g_h1[p];
            for (int i = tid; i < 2048; i += 256) hs4[i] = __ldcg(hsrc + i);
            __syncthreads();
            for (int task = wid0; task < 544; task += NW){
                if (task < 512){
                    dotrow16(Wq + (size_t)task*HH, hs4, bq[task], g_q + task, HH, lane);
                } else if (t > 0){
                    int r = task - 512;
                    dotrow16(Wout + (size_t)r*HH, hs4, bout[r],
                             out + (size_t)(t-1)*VV + r, TT*VV, lane);
                }
            }
        }
        gridbar(ep, NB);

        // ---- phase B: scores[b,tau] = sum_h v[h]*tanh(q[b,h]+Kproj[b,tau,h]) ----
        // warp handles a tau-PAIR with all 8 Kproj vectors prefetched (512B in flight)
        {
            float4* qs4 = (float4*)sm;                 // [16][128] float4
            float*  vs  = sm + NBATCH*HH;              // [512]
            const float4* qsrc = (const float4*)g_q;
            for (int i = tid; i < 2048; i += 256) qs4[i] = __ldcg(qsrc + i);
            for (int i = tid; i < HH;  i += 256) vs[i] = v[i];
            __syncthreads();
            const float4* vs4 = (const float4*)vs;
            for (int pr = wid0; pr < 2048; pr += NW){
                int b = pr >> 7;
                const float4* Ka = (const float4*)(g_Kproj + ((size_t)pr*2)*HH);
                const float4* Kb = Ka + 128;
                float4 ka[4], kb[4];
#pragma unroll
                for (int i = 0; i < 4; i++){
                    ka[i] = __ldcg(Ka + lane + 32*i);
                    kb[i] = __ldcg(Kb + lane + 32*i);
                }
                float a0 = 0.f, a1 = 0.f;
#pragma unroll
                for (int i = 0; i < 4; i++){
                    int c = lane + 32*i;
                    float4 q4 = qs4[b*128 + c];
                    float4 v4 = vs4[c];
                    a0 += v4.x * tanh_fast(q4.x + ka[i].x);
                    a0 += v4.y * tanh_fast(q4.y + ka[i].y);
                    a0 += v4.z * tanh_fast(q4.z + ka[i].z);
                    a0 += v4.w * tanh_fast(q4.w + ka[i].w);
                    a1 += v4.x * tanh_fast(q4.x + kb[i].x);
                    a1 += v4.y * tanh_fast(q4.y + kb[i].y);
                    a1 += v4.z * tanh_fast(q4.z + kb[i].z);
                    a1 += v4.w * tanh_fast(q4.w + kb[i].w);
                }
                a0 = wsum(a0); a1 = wsum(a1);
                if (lane == 0){ g_scores[2*pr] = a0; g_scores[2*pr+1] = a1; }
            }
        }
        gridbar(ep, NB);

        // ---- phase C: softmax over T + ctx = w @ enc (128 tasks: 16b x 8 h-chunks) ----
        {
            float* ws  = sm;          // [256]
            float* red = sm + 256;    // [8]
            float* sP  = sm + 272;    // [256]
            for (int task = bx; task < 128; task += NB){
                int b = task >> 3, hc = (task & 7) * 64;
                float s = g_scores[b*TT + tid];
                float m = wmax(s);
                if (lane == 0) red[w] = m;
                __syncthreads();
                float mx = red[0];
#pragma unroll
                for (int j = 1; j < 8; j++) mx = fmaxf(mx, red[j]);
                float e = __expf(s - mx);
                ws[tid] = e;
                float su = wsum(e);
                if (lane == 0) red[w] = su;
                __syncthreads();
                float tot = red[0];
#pragma unroll
                for (int j = 1; j < 8; j++) tot += red[j];
                float rz = 1.f / tot;
                int h = hc + (tid & 63), stripe = tid >> 6;
                const float* ep_ = enc + ((size_t)(b*TT) + stripe*64)*HH + h;
                float acc = 0.f;
#pragma unroll 8
                for (int tt = 0; tt < 64; tt++) acc += ws[stripe*64 + tt] * __ldcg(ep_ + (size_t)tt*HH);
                sP[tid] = acc; __syncthreads();
                if (tid < 64)
                    g_ctx[b*HH + hc + tid] = (sP[tid] + sP[tid+64] + sP[tid+128] + sP[tid+192]) * rz;
                __syncthreads();
            }
        }
        gridbar(ep, NB);

        // ---- phase D: LSTM layer 0, x = [enc_t | ctx] (K=1024); 1024 tasks (cell, bhalf) ----
        {
            float4* xs4 = (float4*)sm;                    // [16][256] float4 = 64KB
            float4* hs4 = (float4*)(sm + NBATCH*1024);    // [16][128] float4 = 32KB
            const float4* enc4 = (const float4*)enc;
            const float4* ctx4 = (const float4*)g_ctx;
            for (int i = tid; i < 4096; i += 256){
                int b = i >> 8, r = i & 255;
                xs4[i] = (r < 128) ? __ldcg(enc4 + (size_t)(b*TT + t)*128 + r)
                                   : ctx4[b*128 + (r - 128)];
            }
            const float4* hsrc = (const float4*)g_h0[p];
            for (int i = tid; i < 2048; i += 256) hs4[i] = __ldcg(hsrc + i);
            __syncthreads();
            for (int task = wid0; task < 1024; task += NW){
                int cell = task >> 1, bh = task & 1;
                u64 acc[4][8];
#pragma unroll
                for (int g=0; g<4; g++)
#pragma unroll
                    for (int b=0; b<8; b++) acc[g][b] = 0ull;
                accum_half<1024>(acc, Wih0, cell, xs4 + bh*8*256, lane);
                accum_half<512 >(acc, Whh0, cell, hs4 + bh*8*128, lane);
                finish_half(acc, cell, bh, bih0, bhh0, g_c0[p], g_h0[np], g_c0[np], lane);
            }
        }
        gridbar(ep, NB);

        // ---- phase E: LSTM layer 1, x = h0_new (K=512); 1024 tasks ----
        {
            float4* xs4 = (float4*)sm;                    // [16][128] float4
            float4* hs4 = (float4*)(sm + NBATCH*HH);      // [16][128] float4
            const float4* xsrc = (const float4*)g_h0[np];
            const float4* hsrc = (const float4*)g_h1[p];
            for (int i = tid; i < 2048; i += 256){
                xs4[i] = __ldcg(xsrc + i);
                hs4[i] = __ldcg(hsrc + i);
            }
            __syncthreads();
            for (int task = wid0; task < 1024; task += NW){
                int cell = task >> 1, bh = task & 1;
                u64 acc[4][8];
#pragma unroll
                for (int g=0; g<4; g++)
#pragma unroll
                    for (int b=0; b<8; b++) acc[g][b] = 0ull;
                accum_half<512>(acc, Wih1, cell, xs4 + bh*8*128, lane);
                accum_half<512>(acc, Whh1, cell, hs4 + bh*8*128, lane);
                finish_half(acc, cell, bh, bih1, bhh1, g_c1[p], g_h1[np], g_c1[np], lane);
            }
        }
        gridbar(ep, NB);
    }

    // ---- final logits for t = 255 (state parity 0 after step 255) ----
    {
        float4* hs4 = (float4*)sm;
        const float4* hsrc = (const float4*)g_h1[0];
        for (int i = tid; i < 2048; i += 256) hs4[i] = __ldcg(hsrc + i);
        __syncthreads();
        for (int task = wid0; task < 544; task += NW){
            if (task >= 512){
                int r = task - 512;
                dotrow16(Wout + (size_t)r*HH, hs4, bout[r],
                         out + (size_t)(TT-1)*VV + r, TT*VV, lane);
            }
        }
    }

    if (bx == 0 && tid == 0) g_epoch = ep;   // persist epoch base for next launch
}

// ---------------- launch ----------------
extern "C" void kernel_launch(void* const* d_in, const int* in_sizes, int n_in,
                              void* d_out, int out_size){
    const float* enc   = (const float*)d_in[0];
    const float* h0in  = (const float*)d_in[1];
    const float* c0in  = (const float*)d_in[2];
    // d_in[3] = audio_lengths (unused by the reference math)
    const float* Wq    = (const float*)d_in[4];
    const float* bq    = (const float*)d_in[5];
    const float* Wk    = (const float*)d_in[6];
    const float* bk    = (const float*)d_in[7];
    const float* v     = (const float*)d_in[8];
    // d_in[9] = vb (shift-invariant under softmax; omitted)
    const float* Wih0  = (const float*)d_in[10];
    const float* bih0  = (const float*)d_in[11];
    const float* Whh0  = (const float*)d_in[12];
    const float* bhh0  = (const float*)d_in[13];
    const float* Wih1  = (const float*)d_in[14];
    const float* bih1  = (const float*)d_in[15];
    const float* Whh1  = (const float*)d_in[16];
    const float* bhh1  = (const float*)d_in[17];
    const float* Wout  = (const float*)d_in[18];
    const float* bout  = (const float*)d_in[19];
    float* out = (float*)d_out;

    const int SMEM = (NBATCH*1024 + NBATCH*512) * 4;   // 98304 bytes (phase D peak)
    cudaFuncSetAttribute(decoder_persistent, cudaFuncAttributeMaxDynamicSharedMemorySize, SMEM);

    // grid = exactly the number of co-resident blocks (deadlock-proof for any GPU cfg)
    int dev = 0; cudaGetDevice(&dev);
    int nsm = 0; cudaDeviceGetAttribute(&nsm, cudaDevAttrMultiProcessorCount, dev);
    int maxb = 0;
    cudaOccupancyMaxActiveBlocksPerMultiprocessor(&maxb, decoder_persistent, 256, SMEM);
    if (maxb < 1) maxb = 1;
    int grid = nsm * maxb;
    if (grid < 1) grid = 1;
    if (grid > 512) grid = 512;

    decoder_persistent<<<grid, 256, SMEM>>>(enc, h0in, c0in, Wq, bq, Wk, bk, v,
                                            Wih0, bih0, Whh0, bhh0,
                                            Wih1, bih1, Whh1, bhh1,
                                            Wout, bout, out);
}